// round 10
// baseline (speedup 1.0000x reference)
#include <cuda_runtime.h>
#include <cuda_fp16.h>
#include <stdint.h>

#define FXD 64
#define HD 256
#define NTHR 384
#define NW   12

// ---- Precomputed u[b]@W1[128:192] + b1 : [512,256] fp32 ----
__device__ __align__(16) float g_ubb[512 * HD];

__global__ void ubb_kernel(const float* __restrict__ u,
                           const float* __restrict__ W1,
                           const float* __restrict__ b1) {
    __shared__ float us[FXD];
    int b = blockIdx.x, c = threadIdx.x;
    if (c < FXD) us[c] = u[b * FXD + c];
    __syncthreads();
    float acc = b1[c];
#pragma unroll 16
    for (int k = 0; k < FXD; ++k)
        acc = fmaf(us[k], W1[(2 * FXD + k) * HD + c], acc);
    g_ubb[b * HD + c] = acc;
}

__device__ __forceinline__ uint32_t packf16(float a, float b) {
    __half2 h = __floats2half2_rn(a, b);
    return *reinterpret_cast<uint32_t*>(&h);
}

__device__ __forceinline__ void mma16816(float* c, const uint32_t* a,
                                         uint32_t b0, uint32_t b1) {
    asm volatile(
        "mma.sync.aligned.m16n8k16.row.col.f32.f16.f16.f32 "
        "{%0,%1,%2,%3}, {%4,%5,%6,%7}, {%8,%9}, {%0,%1,%2,%3};"
        : "+f"(c[0]), "+f"(c[1]), "+f"(c[2]), "+f"(c[3])
        : "r"(a[0]), "r"(a[1]), "r"(a[2]), "r"(a[3]), "r"(b0), "r"(b1));
}

// SMEM (uint4 units): each uint4 = B-frags for TWO adjacent n-tiles (fp16)
//   w1s: [8 kstep][16 ntpair][32 lane]  = 4096 uint4 (64KB)
//   w2s: [16 kstep][4 ntpair][32 lane]  = 2048 uint4 (32KB)
#define W2_OFF  4096
#define B2_OFF  (4096 + 2048)
#define SMEM_SZ ((4096 + 2048) * 16 + 256)

__global__ __launch_bounds__(NTHR, 1)
void edge_mlp_hmma(const float* __restrict__ src,
                   const float* __restrict__ dst,
                   const int* __restrict__ batch,
                   const float* __restrict__ W1,
                   const float* __restrict__ W2,
                   const float* __restrict__ b2,
                   float* __restrict__ out, int E, int B)
{
    extern __shared__ uint4 smem4[];
    uint4* w1s = smem4;
    uint4* w2s = smem4 + W2_OFF;
    float* b2s = (float*)(smem4 + B2_OFF);

    const int tid  = threadIdx.x;
    const int wid  = tid >> 5;
    const int lane = tid & 31;
    const int gg   = lane >> 2;   // group row
    const int tig  = lane & 3;    // thread in group

    // ---- stage W1 fp16 B-fragments ----
    for (int i = tid; i < 8 * 16 * 32 * 4; i += NTHR) {
        int c = i & 3, t = (i >> 2) & 31, ntp = (i >> 7) & 15, s = i >> 11;
        int h = c >> 1, p = c & 1;
        int n  = (2 * ntp + h) * 8 + (t >> 2);
        int k0 = s * 16 + 2 * (t & 3) + p * 8;
        ((uint32_t*)&w1s[(s * 16 + ntp) * 32 + t])[c] =
            packf16(W1[k0 * HD + n], W1[(k0 + 1) * HD + n]);
    }
    // ---- stage W2 ----
    for (int i = tid; i < 16 * 4 * 32 * 4; i += NTHR) {
        int c = i & 3, t = (i >> 2) & 31, ntp = (i >> 7) & 3, s = i >> 9;
        int h = c >> 1, p = c & 1;
        int n  = (2 * ntp + h) * 8 + (t >> 2);
        int k0 = s * 16 + 2 * (t & 3) + p * 8;
        ((uint32_t*)&w2s[(s * 4 + ntp) * 32 + t])[c] =
            packf16(W2[k0 * 64 + n], W2[(k0 + 1) * 64 + n]);
    }
    if (tid < 64) b2s[tid] = b2[tid];
    __syncthreads();

    // ---- warp-autonomous loop over 32-edge groups ----
    const int ngroups = (E + 31) >> 5;
    const int gw0     = blockIdx.x * NW + wid;
    const int gstride = gridDim.x * NW;

    for (int g = gw0; g < ngroups; g += gstride) {
        const int ebase = g * 32 + gg;     // row 0 of m-tile 0
        // clamped edge ids for safe loads (tail-free when E%32==0)
        uint32_t eo[4];   // byte-row offsets /4 : e*64 (floats)
        uint32_t uo[4];   // ubb row offsets (floats)
#pragma unroll
        for (int j = 0; j < 4; ++j) {
            int e = ebase + 8 * j;
            int ec = e < E ? e : (E - 1);
            eo[j] = (uint32_t)ec * 64u;
            int bi = batch[ec];
            bi = min(max(bi, 0), B - 1);
            uo[j] = (uint32_t)bi * (uint32_t)HD;
        }

        // ---- load A1 fragments: Ah[s][0..3] = mtile0, [4..7] = mtile1 ----
        uint32_t Ah[8][8];
#pragma unroll
        for (int s = 0; s < 8; ++s) {
            const float* xp = (s < 4) ? dst : src;
            const int k = (s & 3) * 16 + 2 * tig;
#pragma unroll
            for (int m = 0; m < 2; ++m) {
                float2 pa0 = *(const float2*)(xp + eo[2 * m]     + k);
                float2 pa1 = *(const float2*)(xp + eo[2 * m]     + k + 8);
                float2 pb0 = *(const float2*)(xp + eo[2 * m + 1] + k);
                float2 pb1 = *(const float2*)(xp + eo[2 * m + 1] + k + 8);
                Ah[s][4 * m + 0] = packf16(pa0.x, pa0.y);
                Ah[s][4 * m + 1] = packf16(pb0.x, pb0.y);
                Ah[s][4 * m + 2] = packf16(pa1.x, pa1.y);
                Ah[s][4 * m + 3] = packf16(pb1.x, pb1.y);
            }
        }

        // C2[(nt2*2 + m)*4 + r] : 32 rows x 64 cols
        float C2[64];
#pragma unroll
        for (int i = 0; i < 64; ++i) C2[i] = 0.f;

        // ---- 16 chunks of 16 hidden cols (chunk == one W2 k-step) ----
#pragma unroll
        for (int c1 = 0; c1 < 16; ++c1) {
            // GEMM1 chunk: C1[(h*2 + m)*4 + r], h = n-tile within chunk
            float C1[16];
#pragma unroll
            for (int i = 0; i < 16; ++i) C1[i] = 0.f;
#pragma unroll
            for (int s = 0; s < 8; ++s) {
                uint4 wv = w1s[(s * 16 + c1) * 32 + lane];
#pragma unroll
                for (int m = 0; m < 2; ++m) {
                    mma16816(C1 + (0 * 2 + m) * 4, Ah[s] + 4 * m, wv.x, wv.y);
                    mma16816(C1 + (1 * 2 + m) * 4, Ah[s] + 4 * m, wv.z, wv.w);
                }
            }

            // ---- epilogue: relu(C1 + ubb) -> A2 frags ----
            uint32_t A2[2][4];
#pragma unroll
            for (int m = 0; m < 2; ++m) {
#pragma unroll
                for (int h = 0; h < 2; ++h) {
                    const int col = c1 * 16 + h * 8 + 2 * tig;
                    float2 ua = *(const float2*)(g_ubb + uo[2 * m]     + col);
                    float2 ub = *(const float2*)(g_ubb + uo[2 * m + 1] + col);
                    const float* cp = C1 + (h * 2 + m) * 4;
                    A2[m][2 * h + 0] = packf16(fmaxf(cp[0] + ua.x, 0.f),
                                               fmaxf(cp[1] + ua.y, 0.f));
                    A2[m][2 * h + 1] = packf16(fmaxf(cp[2] + ub.x, 0.f),
                                               fmaxf(cp[3] + ub.y, 0.f));
                }
            }

            // ---- GEMM2 partial: k-step c1 ----
#pragma unroll
            for (int ntp = 0; ntp < 4; ++ntp) {
                uint4 wv = w2s[(c1 * 4 + ntp) * 32 + lane];
#pragma unroll
                for (int m = 0; m < 2; ++m) {
                    mma16816(C2 + ((2 * ntp + 0) * 2 + m) * 4, A2[m], wv.x, wv.y);
                    mma16816(C2 + ((2 * ntp + 1) * 2 + m) * 4, A2[m], wv.z, wv.w);
                }
            }
        }

        // ---- store out = C2 + b2 (bounds-checked only here) ----
#pragma unroll
        for (int nt2 = 0; nt2 < 8; ++nt2) {
            const int col = nt2 * 8 + 2 * tig;
            const float bx = b2s[col], by = b2s[col + 1];
#pragma unroll
            for (int m = 0; m < 2; ++m) {
                const float* cp = C2 + (nt2 * 2 + m) * 4;
                if (ebase + 16 * m < E) {
                    float2 o; o.x = cp[0] + bx; o.y = cp[1] + by;
                    *(float2*)(out + eo[2 * m] + col) = o;
                }
                if (ebase + 16 * m + 8 < E) {
                    float2 o; o.x = cp[2] + bx; o.y = cp[3] + by;
                    *(float2*)(out + eo[2 * m + 1] + col) = o;
                }
            }
        }
    }
}

extern "C" void kernel_launch(void* const* d_in, const int* in_sizes, int n_in,
                              void* d_out, int out_size) {
    const float* src   = (const float*)d_in[0];
    const float* dest  = (const float*)d_in[1];
    /* d_in[2] = edge_attr, unused by the reference */
    const float* u     = (const float*)d_in[3];
    const int*   batch = (const int*)d_in[4];
    const float* W1    = (const float*)d_in[5];
    const float* b1    = (const float*)d_in[6];
    const float* W2    = (const float*)d_in[7];
    const float* b2    = (const float*)d_in[8];
    float* out = (float*)d_out;

    int E = in_sizes[4];
    int B = in_sizes[3] / FXD;

    ubb_kernel<<<B, 256>>>(u, W1, b1);

    int nsm = 148;
    cudaDeviceGetAttribute(&nsm, cudaDevAttrMultiProcessorCount, 0);
    long ngroups = ((long)E + 31) >> 5;
    long maxcta  = (ngroups + NW - 1) / NW;
    int grid = (int)(maxcta < (long)nsm ? maxcta : (long)nsm);

    cudaFuncSetAttribute(edge_mlp_hmma,
                         cudaFuncAttributeMaxDynamicSharedMemorySize, SMEM_SZ);
    edge_mlp_hmma<<<grid, NTHR, SMEM_SZ>>>(src, dest, batch, W1, W2, b2, out, E, B);
}

// round 11
// speedup vs baseline: 1.0396x; 1.0396x over previous
#include <cuda_runtime.h>
#include <cuda_fp16.h>
#include <stdint.h>

#define FXD 64
#define HD 256
#define NTHR 256
#define NW   8

// ---- Precomputed u[b]@W1[128:192] + b1 : [512,256] fp32 ----
__device__ __align__(16) float g_ubb[512 * HD];

__global__ void ubb_kernel(const float* __restrict__ u,
                           const float* __restrict__ W1,
                           const float* __restrict__ b1) {
    __shared__ float us[FXD];
    int b = blockIdx.x, c = threadIdx.x;
    if (c < FXD) us[c] = u[b * FXD + c];
    __syncthreads();
    float acc = b1[c];
#pragma unroll 16
    for (int k = 0; k < FXD; ++k)
        acc = fmaf(us[k], W1[(2 * FXD + k) * HD + c], acc);
    g_ubb[b * HD + c] = acc;
}

__device__ __forceinline__ uint32_t packf16(float a, float b) {
    __half2 h = __floats2half2_rn(a, b);
    return *reinterpret_cast<uint32_t*>(&h);
}

__device__ __forceinline__ void mma16816(float* c, const uint32_t* a,
                                         uint32_t b0, uint32_t b1) {
    asm volatile(
        "mma.sync.aligned.m16n8k16.row.col.f32.f16.f16.f32 "
        "{%0,%1,%2,%3}, {%4,%5,%6,%7}, {%8,%9}, {%0,%1,%2,%3};"
        : "+f"(c[0]), "+f"(c[1]), "+f"(c[2]), "+f"(c[3])
        : "r"(a[0]), "r"(a[1]), "r"(a[2]), "r"(a[3]), "r"(b0), "r"(b1));
}

// SMEM (uint4 units): each uint4 = B-frags for TWO adjacent n-tiles (fp16)
//   w1s: [8 kstep][16 ntpair][32 lane]  = 4096 uint4 (64KB)
//   w2s: [16 kstep][4 ntpair][32 lane]  = 2048 uint4 (32KB)
#define W2_OFF  4096
#define B2_OFF  (4096 + 2048)
#define SMEM_SZ ((4096 + 2048) * 16 + 256)

__global__ __launch_bounds__(NTHR, 1)
void edge_mlp_hmma(const float* __restrict__ src,
                   const float* __restrict__ dst,
                   const int* __restrict__ batch,
                   const float* __restrict__ W1,
                   const float* __restrict__ W2,
                   const float* __restrict__ b2,
                   float* __restrict__ out, int E, int B)
{
    extern __shared__ uint4 smem4[];
    uint4* w1s = smem4;
    uint4* w2s = smem4 + W2_OFF;
    float* b2s = (float*)(smem4 + B2_OFF);

    const int tid  = threadIdx.x;
    const int wid  = tid >> 5;
    const int lane = tid & 31;
    const int gg   = lane >> 2;   // group row
    const int tig  = lane & 3;    // thread in group

    // ---- stage W1 fp16 B-fragments ----
    for (int i = tid; i < 8 * 16 * 32 * 4; i += NTHR) {
        int c = i & 3, t = (i >> 2) & 31, ntp = (i >> 7) & 15, s = i >> 11;
        int h = c >> 1, p = c & 1;
        int n  = (2 * ntp + h) * 8 + (t >> 2);
        int k0 = s * 16 + 2 * (t & 3) + p * 8;
        ((uint32_t*)&w1s[(s * 16 + ntp) * 32 + t])[c] =
            packf16(W1[k0 * HD + n], W1[(k0 + 1) * HD + n]);
    }
    // ---- stage W2 ----
    for (int i = tid; i < 16 * 4 * 32 * 4; i += NTHR) {
        int c = i & 3, t = (i >> 2) & 31, ntp = (i >> 7) & 3, s = i >> 9;
        int h = c >> 1, p = c & 1;
        int n  = (2 * ntp + h) * 8 + (t >> 2);
        int k0 = s * 16 + 2 * (t & 3) + p * 8;
        ((uint32_t*)&w2s[(s * 4 + ntp) * 32 + t])[c] =
            packf16(W2[k0 * 64 + n], W2[(k0 + 1) * 64 + n]);
    }
    if (tid < 64) b2s[tid] = b2[tid];
    __syncthreads();

    // ---- warp-autonomous loop over 32-edge groups ----
    const int ngroups = (E + 31) >> 5;
    const int gw0     = blockIdx.x * NW + wid;
    const int gstride = gridDim.x * NW;

    for (int g = gw0; g < ngroups; g += gstride) {
        const int ebase = g * 32 + gg;
        uint32_t eo[4];   // x row offsets (floats)
        uint32_t uo[4];   // ubb row offsets (floats)
#pragma unroll
        for (int j = 0; j < 4; ++j) {
            int e = ebase + 8 * j;
            int ec = e < E ? e : (E - 1);
            eo[j] = (uint32_t)ec * 64u;
            int bi = batch[ec];
            bi = min(max(bi, 0), B - 1);
            uo[j] = (uint32_t)bi * (uint32_t)HD;
        }

        // ---- load A1 fragments: Ah[s][0..3] = mtile0, [4..7] = mtile1 ----
        uint32_t Ah[8][8];
#pragma unroll
        for (int s = 0; s < 8; ++s) {
            const float* xp = (s < 4) ? dst : src;
            const int k = (s & 3) * 16 + 2 * tig;
#pragma unroll
            for (int m = 0; m < 2; ++m) {
                float2 pa0 = *(const float2*)(xp + eo[2 * m]     + k);
                float2 pa1 = *(const float2*)(xp + eo[2 * m]     + k + 8);
                float2 pb0 = *(const float2*)(xp + eo[2 * m + 1] + k);
                float2 pb1 = *(const float2*)(xp + eo[2 * m + 1] + k + 8);
                Ah[s][4 * m + 0] = packf16(pa0.x, pa0.y);
                Ah[s][4 * m + 1] = packf16(pb0.x, pb0.y);
                Ah[s][4 * m + 2] = packf16(pa1.x, pa1.y);
                Ah[s][4 * m + 3] = packf16(pb1.x, pb1.y);
            }
        }

        // C2[(nt2*2 + m)*4 + r] : 32 rows x 64 cols
        float C2[64];
#pragma unroll
        for (int i = 0; i < 64; ++i) C2[i] = 0.f;

        // ---- 16 chunks of 16 hidden cols (chunk == one W2 k-step) ----
#pragma unroll
        for (int c1 = 0; c1 < 16; ++c1) {
            // (1) prefetch ubb operands for this chunk's epilogue FIRST
            float2 U[2][2][2];   // [m][h][row-in-pair]
#pragma unroll
            for (int m = 0; m < 2; ++m)
#pragma unroll
                for (int h = 0; h < 2; ++h) {
                    const int col = c1 * 16 + h * 8 + 2 * tig;
                    U[m][h][0] = *(const float2*)(g_ubb + uo[2 * m]     + col);
                    U[m][h][1] = *(const float2*)(g_ubb + uo[2 * m + 1] + col);
                }

            // (2) GEMM1 chunk with double-buffered weight fragments
            float C1[16];
#pragma unroll
            for (int i = 0; i < 16; ++i) C1[i] = 0.f;
            uint4 wv = w1s[(0 * 16 + c1) * 32 + lane];
#pragma unroll
            for (int s = 0; s < 8; ++s) {
                uint4 wvn;
                if (s < 7) wvn = w1s[((s + 1) * 16 + c1) * 32 + lane];
#pragma unroll
                for (int m = 0; m < 2; ++m) {
                    mma16816(C1 + (0 * 2 + m) * 4, Ah[s] + 4 * m, wv.x, wv.y);
                    mma16816(C1 + (1 * 2 + m) * 4, Ah[s] + 4 * m, wv.z, wv.w);
                }
                wv = wvn;
            }

            // (3) preload GEMM2 fragments before the epilogue ALU chain
            uint4 wv2[4];
#pragma unroll
            for (int ntp = 0; ntp < 4; ++ntp)
                wv2[ntp] = w2s[(c1 * 4 + ntp) * 32 + lane];

            // (4) epilogue: relu(C1 + ubb) -> A2 frags
            uint32_t A2[2][4];
#pragma unroll
            for (int m = 0; m < 2; ++m) {
#pragma unroll
                for (int h = 0; h < 2; ++h) {
                    const float* cp = C1 + (h * 2 + m) * 4;
                    A2[m][2 * h + 0] = packf16(fmaxf(cp[0] + U[m][h][0].x, 0.f),
                                               fmaxf(cp[1] + U[m][h][0].y, 0.f));
                    A2[m][2 * h + 1] = packf16(fmaxf(cp[2] + U[m][h][1].x, 0.f),
                                               fmaxf(cp[3] + U[m][h][1].y, 0.f));
                }
            }

            // (5) GEMM2 partial: k-step c1
#pragma unroll
            for (int ntp = 0; ntp < 4; ++ntp) {
#pragma unroll
                for (int m = 0; m < 2; ++m) {
                    mma16816(C2 + ((2 * ntp + 0) * 2 + m) * 4, A2[m], wv2[ntp].x, wv2[ntp].y);
                    mma16816(C2 + ((2 * ntp + 1) * 2 + m) * 4, A2[m], wv2[ntp].z, wv2[ntp].w);
                }
            }
        }

        // ---- store out = C2 + b2 ----
#pragma unroll
        for (int nt2 = 0; nt2 < 8; ++nt2) {
            const int col = nt2 * 8 + 2 * tig;
            const float bx = b2s[col], by = b2s[col + 1];
#pragma unroll
            for (int m = 0; m < 2; ++m) {
                const float* cp = C2 + (nt2 * 2 + m) * 4;
                if (ebase + 16 * m < E) {
                    float2 o; o.x = cp[0] + bx; o.y = cp[1] + by;
                    *(float2*)(out + eo[2 * m] + col) = o;
                }
                if (ebase + 16 * m + 8 < E) {
                    float2 o; o.x = cp[2] + bx; o.y = cp[3] + by;
                    *(float2*)(out + eo[2 * m + 1] + col) = o;
                }
            }
        }
    }
}

extern "C" void kernel_launch(void* const* d_in, const int* in_sizes, int n_in,
                              void* d_out, int out_size) {
    const float* src   = (const float*)d_in[0];
    const float* dest  = (const float*)d_in[1];
    /* d_in[2] = edge_attr, unused by the reference */
    const float* u     = (const float*)d_in[3];
    const int*   batch = (const int*)d_in[4];
    const float* W1    = (const float*)d_in[5];
    const float* b1    = (const float*)d_in[6];
    const float* W2    = (const float*)d_in[7];
    const float* b2    = (const float*)d_in[8];
    float* out = (float*)d_out;

    int E = in_sizes[4];
    int B = in_sizes[3] / FXD;

    ubb_kernel<<<B, 256>>>(u, W1, b1);

    int nsm = 148;
    cudaDeviceGetAttribute(&nsm, cudaDevAttrMultiProcessorCount, 0);
    long ngroups = ((long)E + 31) >> 5;
    long maxcta  = (ngroups + NW - 1) / NW;
    int grid = (int)(maxcta < (long)nsm ? maxcta : (long)nsm);

    cudaFuncSetAttribute(edge_mlp_hmma,
                         cudaFuncAttributeMaxDynamicSharedMemorySize, SMEM_SZ);
    edge_mlp_hmma<<<grid, NTHR, SMEM_SZ>>>(src, dest, batch, W1, W2, b2, out, E, B);
}

// round 12
// speedup vs baseline: 1.0565x; 1.0162x over previous
#include <cuda_runtime.h>
#include <cuda_fp16.h>
#include <stdint.h>

#define FXD 64
#define HD 256
#define NTHR 256
#define NW   8

// ---- Precomputed u[b]@W1[128:192] + b1 : [512,128] half2 ----
__device__ __align__(16) __half2 g_ubbh[512 * 128];

__global__ void ubb_kernel(const float* __restrict__ u,
                           const float* __restrict__ W1,
                           const float* __restrict__ b1) {
    __shared__ float us[FXD];
    __shared__ float accs[HD];
    int b = blockIdx.x, c = threadIdx.x;
    if (c < FXD) us[c] = u[b * FXD + c];
    __syncthreads();
    float acc = b1[c];
#pragma unroll 16
    for (int k = 0; k < FXD; ++k)
        acc = fmaf(us[k], W1[(2 * FXD + k) * HD + c], acc);
    accs[c] = acc;
    __syncthreads();
    if (c < 128)
        g_ubbh[b * 128 + c] = __floats2half2_rn(accs[2 * c], accs[2 * c + 1]);
}

__device__ __forceinline__ uint32_t packf16(float a, float b) {
    __half2 h = __floats2half2_rn(a, b);
    return *reinterpret_cast<uint32_t*>(&h);
}

__device__ __forceinline__ void mma16816(float* c, const uint32_t* a,
                                         uint32_t b0, uint32_t b1) {
    asm volatile(
        "mma.sync.aligned.m16n8k16.row.col.f32.f16.f16.f32 "
        "{%0,%1,%2,%3}, {%4,%5,%6,%7}, {%8,%9}, {%0,%1,%2,%3};"
        : "+f"(c[0]), "+f"(c[1]), "+f"(c[2]), "+f"(c[3])
        : "r"(a[0]), "r"(a[1]), "r"(a[2]), "r"(a[3]), "r"(b0), "r"(b1));
}

// SMEM (uint4 units):
//   w1s 4096 (64KB), w2s 2048 (32KB), outbuf 8 warps x 32x68 floats (68KB), b2 64 floats
#define W2_OFF   4096
#define OUT_OFF  6144
#define B2_OFF   (6144 + 4352)
#define SMEM_SZ  ((6144 + 4352 + 16) * 16)
#define OSTRIDE  68

__global__ __launch_bounds__(NTHR, 1)
void edge_mlp_hmma(const float* __restrict__ src,
                   const float* __restrict__ dst,
                   const int* __restrict__ batch,
                   const float* __restrict__ W1,
                   const float* __restrict__ W2,
                   const float* __restrict__ b2,
                   float* __restrict__ out, int E, int B)
{
    extern __shared__ uint4 smem4[];
    uint4* w1s = smem4;
    uint4* w2s = smem4 + W2_OFF;
    float* b2s = (float*)(smem4 + B2_OFF);

    const int tid  = threadIdx.x;
    const int wid  = tid >> 5;
    const int lane = tid & 31;
    const int gg   = lane >> 2;   // group row
    const int tig  = lane & 3;    // thread in group

    float* outs = (float*)(smem4 + OUT_OFF) + wid * (32 * OSTRIDE);

    // ---- stage W1 fp16 B-fragments ----
    for (int i = tid; i < 8 * 16 * 32 * 4; i += NTHR) {
        int c = i & 3, t = (i >> 2) & 31, ntp = (i >> 7) & 15, s = i >> 11;
        int h = c >> 1, p = c & 1;
        int n  = (2 * ntp + h) * 8 + (t >> 2);
        int k0 = s * 16 + 2 * (t & 3) + p * 8;
        ((uint32_t*)&w1s[(s * 16 + ntp) * 32 + t])[c] =
            packf16(W1[k0 * HD + n], W1[(k0 + 1) * HD + n]);
    }
    // ---- stage W2 ----
    for (int i = tid; i < 16 * 4 * 32 * 4; i += NTHR) {
        int c = i & 3, t = (i >> 2) & 31, ntp = (i >> 7) & 3, s = i >> 9;
        int h = c >> 1, p = c & 1;
        int n  = (2 * ntp + h) * 8 + (t >> 2);
        int k0 = s * 16 + 2 * (t & 3) + p * 8;
        ((uint32_t*)&w2s[(s * 4 + ntp) * 32 + t])[c] =
            packf16(W2[k0 * 64 + n], W2[(k0 + 1) * 64 + n]);
    }
    if (tid < 64) b2s[tid] = b2[tid];
    __syncthreads();

    // ---- warp-autonomous loop over 32-edge groups ----
    const int ngroups = (E + 31) >> 5;
    const int gw0     = blockIdx.x * NW + wid;
    const int gstride = gridDim.x * NW;

    for (int g = gw0; g < ngroups; g += gstride) {
        const int ebase = g * 32 + gg;
        uint32_t eo[4];   // x row offsets (floats)
        uint32_t uo[4];   // ubbh row offsets (half2)
#pragma unroll
        for (int j = 0; j < 4; ++j) {
            int e = ebase + 8 * j;
            int ec = e < E ? e : (E - 1);
            eo[j] = (uint32_t)ec * 64u;
            int bi = batch[ec];
            bi = min(max(bi, 0), B - 1);
            uo[j] = (uint32_t)bi * 128u;
        }

        // ---- load A1 fragments: Ah[s][0..3] = mtile0, [4..7] = mtile1 ----
        uint32_t Ah[8][8];
#pragma unroll
        for (int s = 0; s < 8; ++s) {
            const float* xp = (s < 4) ? dst : src;
            const int k = (s & 3) * 16 + 2 * tig;
#pragma unroll
            for (int m = 0; m < 2; ++m) {
                float2 pa0 = *(const float2*)(xp + eo[2 * m]     + k);
                float2 pa1 = *(const float2*)(xp + eo[2 * m]     + k + 8);
                float2 pb0 = *(const float2*)(xp + eo[2 * m + 1] + k);
                float2 pb1 = *(const float2*)(xp + eo[2 * m + 1] + k + 8);
                Ah[s][4 * m + 0] = packf16(pa0.x, pa0.y);
                Ah[s][4 * m + 1] = packf16(pb0.x, pb0.y);
                Ah[s][4 * m + 2] = packf16(pa1.x, pa1.y);
                Ah[s][4 * m + 3] = packf16(pb1.x, pb1.y);
            }
        }

        // C2[(nt2*2 + m)*4 + r] : 32 rows x 64 cols
        float C2[64];
#pragma unroll
        for (int i = 0; i < 64; ++i) C2[i] = 0.f;

        // ---- 16 chunks of 16 hidden cols (chunk == one W2 k-step) ----
#pragma unroll
        for (int c1 = 0; c1 < 16; ++c1) {
            // (1) prefetch ubb half2 operands
            __half2 U[2][2][2];
#pragma unroll
            for (int m = 0; m < 2; ++m)
#pragma unroll
                for (int h = 0; h < 2; ++h) {
                    const int ci = c1 * 8 + h * 4 + tig;
                    U[m][h][0] = g_ubbh[uo[2 * m]     + ci];
                    U[m][h][1] = g_ubbh[uo[2 * m + 1] + ci];
                }

            // (2) GEMM1 chunk with double-buffered weight fragments
            float C1[16];
#pragma unroll
            for (int i = 0; i < 16; ++i) C1[i] = 0.f;
            uint4 wv = w1s[(0 * 16 + c1) * 32 + lane];
#pragma unroll
            for (int s = 0; s < 8; ++s) {
                uint4 wvn;
                if (s < 7) wvn = w1s[((s + 1) * 16 + c1) * 32 + lane];
#pragma unroll
                for (int m = 0; m < 2; ++m) {
                    mma16816(C1 + (0 * 2 + m) * 4, Ah[s] + 4 * m, wv.x, wv.y);
                    mma16816(C1 + (1 * 2 + m) * 4, Ah[s] + 4 * m, wv.z, wv.w);
                }
                wv = wvn;
            }

            // (3) preload GEMM2 fragments
            uint4 wv2[4];
#pragma unroll
            for (int ntp = 0; ntp < 4; ++ntp)
                wv2[ntp] = w2s[(c1 * 4 + ntp) * 32 + lane];

            // (4) epilogue in half2: A2 = relu(f16(C1) + ubbh)
            uint32_t A2[2][4];
            const __half2 hz = __floats2half2_rn(0.f, 0.f);
#pragma unroll
            for (int m = 0; m < 2; ++m) {
#pragma unroll
                for (int h = 0; h < 2; ++h) {
                    const float* cp = C1 + (h * 2 + m) * 4;
                    __half2 t0 = __hmax2(__hadd2(__floats2half2_rn(cp[0], cp[1]), U[m][h][0]), hz);
                    __half2 t1 = __hmax2(__hadd2(__floats2half2_rn(cp[2], cp[3]), U[m][h][1]), hz);
                    A2[m][2 * h + 0] = *reinterpret_cast<uint32_t*>(&t0);
                    A2[m][2 * h + 1] = *reinterpret_cast<uint32_t*>(&t1);
                }
            }

            // (5) GEMM2 partial: k-step c1
#pragma unroll
            for (int ntp = 0; ntp < 4; ++ntp) {
#pragma unroll
                for (int m = 0; m < 2; ++m) {
                    mma16816(C2 + ((2 * ntp + 0) * 2 + m) * 4, A2[m], wv2[ntp].x, wv2[ntp].y);
                    mma16816(C2 + ((2 * ntp + 1) * 2 + m) * 4, A2[m], wv2[ntp].z, wv2[ntp].w);
                }
            }
        }

        // ---- store: stage C2 in smem, then coalesced STG.128 ----
        if (g * 32 + 32 <= E) {
            __syncwarp();
#pragma unroll
            for (int nt2 = 0; nt2 < 8; ++nt2) {
                const int col = nt2 * 8 + 2 * tig;
#pragma unroll
                for (int m = 0; m < 2; ++m) {
                    const float* cp = C2 + (nt2 * 2 + m) * 4;
                    const int r0 = 16 * m + gg;
                    *(float2*)(outs + r0 * OSTRIDE + col)       = make_float2(cp[0], cp[1]);
                    *(float2*)(outs + (r0 + 8) * OSTRIDE + col) = make_float2(cp[2], cp[3]);
                }
            }
            __syncwarp();
            float* og = out + (uint32_t)g * 2048u;
            const float4* b2v = (const float4*)b2s;
#pragma unroll
            for (int t = 0; t < 16; ++t) {
                int idx = t * 32 + lane;
                int r = idx >> 4, c4 = idx & 15;
                float4 v = *(const float4*)(outs + r * OSTRIDE + c4 * 4);
                float4 bb = b2v[c4];
                v.x += bb.x; v.y += bb.y; v.z += bb.z; v.w += bb.w;
                *(float4*)(og + idx * 4) = v;
            }
            __syncwarp();
        } else {
            // tail fallback (unused when E % 32 == 0)
#pragma unroll
            for (int nt2 = 0; nt2 < 8; ++nt2) {
                const int col = nt2 * 8 + 2 * tig;
                const float bx = b2s[col], by = b2s[col + 1];
#pragma unroll
                for (int m = 0; m < 2; ++m) {
                    const float* cp = C2 + (nt2 * 2 + m) * 4;
                    if (ebase + 16 * m < E) {
                        float2 o; o.x = cp[0] + bx; o.y = cp[1] + by;
                        *(float2*)(out + eo[2 * m] + col) = o;
                    }
                    if (ebase + 16 * m + 8 < E) {
                        float2 o; o.x = cp[2] + bx; o.y = cp[3] + by;
                        *(float2*)(out + eo[2 * m + 1] + col) = o;
                    }
                }
            }
        }
    }
}

extern "C" void kernel_launch(void* const* d_in, const int* in_sizes, int n_in,
                              void* d_out, int out_size) {
    const float* src   = (const float*)d_in[0];
    const float* dest  = (const float*)d_in[1];
    /* d_in[2] = edge_attr, unused by the reference */
    const float* u     = (const float*)d_in[3];
    const int*   batch = (const int*)d_in[4];
    const float* W1    = (const float*)d_in[5];
    const float* b1    = (const float*)d_in[6];
    const float* W2    = (const float*)d_in[7];
    const float* b2    = (const float*)d_in[8];
    float* out = (float*)d_out;

    int E = in_sizes[4];
    int B = in_sizes[3] / FXD;

    ubb_kernel<<<B, 256>>>(u, W1, b1);

    int nsm = 148;
    cudaDeviceGetAttribute(&nsm, cudaDevAttrMultiProcessorCount, 0);
    long ngroups = ((long)E + 31) >> 5;
    long maxcta  = (ngroups + NW - 1) / NW;
    int grid = (int)(maxcta < (long)nsm ? maxcta : (long)nsm);

    cudaFuncSetAttribute(edge_mlp_hmma,
                         cudaFuncAttributeMaxDynamicSharedMemorySize, SMEM_SZ);
    edge_mlp_hmma<<<grid, NTHR, SMEM_SZ>>>(src, dest, batch, W1, W2, b2, out, E, B);
}